// round 1
// baseline (speedup 1.0000x reference)
#include <cuda_runtime.h>

// out[m,o] = sum_c |x[m,c] - w[c,o]| + b[o]
//          = 2*sum_c max(x[m,c], w[c,o]) - Sx[m] - Sw[o] + b[o]
// Inner loop: FMNMX (alu pipe) + FADD (fma pipe) -> dual-pipe balanced, 1 MAC / 2cyc / SMSP.

constexpr int C    = 64;    // channels (reduction dim)
constexpr int OUTC = 128;   // output channels
constexpr int BM   = 64;    // rows per block
constexpr int BO   = 64;    // output cols per block
constexpr int XS   = 68;    // padded stride for transposed x tile (16B-aligned rows)

__global__ __launch_bounds__(256)
void lp1_maxtrick_kernel(const float* __restrict__ x,
                         const float* __restrict__ w,
                         const float* __restrict__ b,
                         float* __restrict__ out)
{
    __shared__ float w_s[C * BO];   // [c][o]  16 KB
    __shared__ float x_s[C * XS];   // [c][m]  17.4 KB (transposed, padded)
    __shared__ float sx_s[BM];      // row sums of x tile
    __shared__ float beta_s[BO];    // b[o] - Sw[o]

    const int tid   = threadIdx.x;
    const int m_blk = blockIdx.x * BM;
    const int o_blk = blockIdx.y * BO;

    // ---- stage w slice [C][BO] (coalesced float4) ----
    #pragma unroll
    for (int i = 0; i < 4; ++i) {
        int idx = tid + 256 * i;            // 1024 float4 total
        int c   = idx >> 4;                 // 16 float4 per c-row
        int o4  = idx & 15;
        float4 v = *(const float4*)(w + c * OUTC + o_blk + o4 * 4);
        *(float4*)(&w_s[c * BO + o4 * 4]) = v;
    }

    // ---- stage x tile transposed: x_s[c][m] (coalesced gmem read) ----
    #pragma unroll
    for (int i = 0; i < 4; ++i) {
        int idx = tid + 256 * i;            // 1024 float4 total
        int m   = idx >> 4;                 // 16 float4 per row
        int c   = (idx & 15) << 2;
        float4 v = *(const float4*)(x + (size_t)(m_blk + m) * C + c);
        x_s[(c + 0) * XS + m] = v.x;
        x_s[(c + 1) * XS + m] = v.y;
        x_s[(c + 2) * XS + m] = v.z;
        x_s[(c + 3) * XS + m] = v.w;
    }
    __syncthreads();

    // ---- prologue: beta[o] = b[o] - Sw[o]; sx[m] = sum_c x ----
    if (tid < BO) {
        float s = 0.f;
        #pragma unroll
        for (int c = 0; c < C; ++c) s += w_s[c * BO + tid];
        beta_s[tid] = b[o_blk + tid] - s;
    } else if (tid < BO + BM) {
        int m = tid - BO;
        float s = 0.f;
        #pragma unroll
        for (int c = 0; c < C; ++c) s += x_s[c * XS + m];
        sx_s[m] = s;
    }
    __syncthreads();

    // ---- main loop: 4x4 register tile of sum_c max(x, w) ----
    const int o0 = (tid & 15) * 4;   // 16 o-groups
    const int m0 = (tid >> 4) * 4;   // 16 m-groups (2 per warp -> LDS broadcast)

    float acc[4][4];
    #pragma unroll
    for (int i = 0; i < 4; ++i)
        #pragma unroll
        for (int j = 0; j < 4; ++j) acc[i][j] = 0.f;

    #pragma unroll 16
    for (int c = 0; c < C; ++c) {
        float4 xv = *(const float4*)(&x_s[c * XS + m0]);
        float4 wv = *(const float4*)(&w_s[c * BO + o0]);
        float xa[4] = {xv.x, xv.y, xv.z, xv.w};
        float wa[4] = {wv.x, wv.y, wv.z, wv.w};
        #pragma unroll
        for (int i = 0; i < 4; ++i)
            #pragma unroll
            for (int j = 0; j < 4; ++j)
                acc[i][j] += fmaxf(xa[i], wa[j]);   // FMNMX (alu) + FADD (fma)
    }

    // ---- epilogue: out = 2*acc - sx + beta, coalesced float4 stores ----
    float bet[4];
    #pragma unroll
    for (int j = 0; j < 4; ++j) bet[j] = beta_s[o0 + j];

    #pragma unroll
    for (int i = 0; i < 4; ++i) {
        float base = -sx_s[m0 + i];
        float4 r;
        r.x = fmaf(2.f, acc[i][0], base + bet[0]);
        r.y = fmaf(2.f, acc[i][1], base + bet[1]);
        r.z = fmaf(2.f, acc[i][2], base + bet[2]);
        r.w = fmaf(2.f, acc[i][3], base + bet[3]);
        *(float4*)(out + (size_t)(m_blk + m0 + i) * OUTC + o_blk + o0) = r;
    }
}

extern "C" void kernel_launch(void* const* d_in, const int* in_sizes, int n_in,
                              void* d_out, int out_size)
{
    const float* x = (const float*)d_in[0];   // (N,H,W,C) fp32 -> [M, 64]
    const float* w = (const float*)d_in[1];   // [64, 128]
    const float* b = (const float*)d_in[2];   // [128]
    float* out = (float*)d_out;               // [M, 128]

    int M = in_sizes[0] / C;                  // 25088
    dim3 grid(M / BM, OUTC / BO);             // (392, 2)
    lp1_maxtrick_kernel<<<grid, 256>>>(x, w, b, out);
}